// round 1
// baseline (speedup 1.0000x reference)
#include <cuda_runtime.h>

// ---------------------------------------------------------------------------
// MPNN forward (embed -> 3x [edge MLP msg + scatter-add + GRU] -> Set2Set(6) ->
// regressor), all fp32, graph-capturable, allocation-free.
// ---------------------------------------------------------------------------

#define N_NODES 50000
#define N_EDGES 800000
#define NODE_DIM 32
#define EDGE_DIM 16
#define HID 64
#define MSG_HID 128
#define NUM_GRAPHS 512
#define NUM_MP 3
#define S2S_STEPS 6
#define IN_DIM (2 * HID + EDGE_DIM)  // 144

// ------------------------- scratch (device globals) ------------------------
__device__ float g_x[N_NODES * HID];        // node state (x == h)
__device__ float g_m[N_NODES * HID];        // aggregated messages
__device__ float g_qh[NUM_GRAPHS * HID];
__device__ float g_qc[NUM_GRAPHS * HID];
__device__ float g_qstar[NUM_GRAPHS * 2 * HID];
__device__ float g_e[N_NODES];
__device__ float g_a[N_NODES];
__device__ unsigned g_emax[NUM_GRAPHS];     // order-encoded float max
__device__ float g_asum[NUM_GRAPHS];
__device__ float g_rvec[NUM_GRAPHS * HID];

__device__ __forceinline__ float sigmoidf_(float x) { return 1.f / (1.f + expf(-x)); }

// monotone float <-> uint encoding for atomicMax
__device__ __forceinline__ unsigned enc_f(float f) {
    unsigned u = __float_as_uint(f);
    return (u & 0x80000000u) ? ~u : (u | 0x80000000u);
}
__device__ __forceinline__ float dec_f(unsigned k) {
    return (k & 0x80000000u) ? __uint_as_float(k & 0x7fffffffu)
                             : __uint_as_float(~k);
}

// ------------------------------ zero kernels -------------------------------
__global__ void zero_m_kernel() {
    int t = blockIdx.x * blockDim.x + threadIdx.x;
    if (t < N_NODES * HID) g_m[t] = 0.f;
}
__global__ void zero_s2s_state_kernel() {
    int t = blockIdx.x * blockDim.x + threadIdx.x;
    if (t < NUM_GRAPHS * HID) { g_qh[t] = 0.f; g_qc[t] = 0.f; }
    if (t < NUM_GRAPHS * 2 * HID) g_qstar[t] = 0.f;
}
__global__ void zero_attn_kernel() {
    int t = blockIdx.x * blockDim.x + threadIdx.x;
    if (t < NUM_GRAPHS) { g_emax[t] = 0u; g_asum[t] = 0.f; }
    if (t < NUM_GRAPHS * HID) g_rvec[t] = 0.f;
}

// ------------------------------- embedding ---------------------------------
__global__ void embed_kernel(const float* __restrict__ xf,
                             const float* __restrict__ W,
                             const float* __restrict__ b) {
    int t = blockIdx.x * blockDim.x + threadIdx.x;
    if (t >= N_NODES * HID) return;
    int v = t >> 6, o = t & 63;
    const float* xr = xf + v * NODE_DIM;
    float acc = b[o];
#pragma unroll
    for (int c = 0; c < NODE_DIM; c++) acc += xr[c] * W[c * HID + o];
    g_x[t] = acc;
}

// ------------------------- edge message MLP kernel -------------------------
// Per warp: EQ edges at a time (weight reuse x EQ). Weights resident in smem.
#define EK_THREADS 512
#define EK_WARPS 16
#define EQ 4
#define EK_SMEM_FLOATS (IN_DIM * MSG_HID + MSG_HID + MSG_HID * HID + HID + \
                        EK_WARPS * EQ * IN_DIM + EK_WARPS * EQ * MSG_HID)

__global__ __launch_bounds__(EK_THREADS, 1)
void edge_msg_kernel(const int* __restrict__ ei, const float* __restrict__ ea,
                     const float* __restrict__ W1, const float* __restrict__ b1,
                     const float* __restrict__ W2, const float* __restrict__ b2) {
    extern __shared__ float smem[];
    float* W1s  = smem;                              // 144*128
    float* b1s  = W1s + IN_DIM * MSG_HID;            // 128
    float* W2s  = b1s + MSG_HID;                     // 128*64
    float* b2s  = W2s + MSG_HID * HID;               // 64
    float* in_s = b2s + HID;                         // EK_WARPS*EQ*144
    float* hid_s = in_s + EK_WARPS * EQ * IN_DIM;    // EK_WARPS*EQ*128

    int tid = threadIdx.x;
    for (int i = tid; i < IN_DIM * MSG_HID; i += EK_THREADS) W1s[i] = W1[i];
    for (int i = tid; i < MSG_HID; i += EK_THREADS) b1s[i] = b1[i];
    for (int i = tid; i < MSG_HID * HID; i += EK_THREADS) W2s[i] = W2[i];
    for (int i = tid; i < HID; i += EK_THREADS) b2s[i] = b2[i];
    __syncthreads();

    int warp = tid >> 5, lane = tid & 31;
    float* win  = in_s + warp * EQ * IN_DIM;
    float* whid = hid_s + warp * EQ * MSG_HID;
    const int* src = ei;
    const int* dst = ei + N_EDGES;

    const int nquads = N_EDGES / EQ;
    for (int q = blockIdx.x * EK_WARPS + warp; q < nquads;
         q += gridDim.x * EK_WARPS) {
        int e0 = q * EQ;
        int d[EQ];
        // stage inputs: [x[dst](64) | x[src](64) | edge_attr(16)]
#pragma unroll
        for (int k = 0; k < EQ; k++) {
            int e = e0 + k;
            int s = src[e];
            int dd = dst[e];
            d[k] = dd;
            const float* xd = g_x + dd * HID;
            const float* xs = g_x + s * HID;
#pragma unroll
            for (int j = 0; j < 5; j++) {
                int idx = lane + 32 * j;
                if (idx < IN_DIM) {
                    float v;
                    if (idx < HID) v = xd[idx];
                    else if (idx < 2 * HID) v = xs[idx - HID];
                    else v = ea[e * EDGE_DIM + (idx - 2 * HID)];
                    win[k * IN_DIM + idx] = v;
                }
            }
        }
        __syncwarp();

        // hidden layer: lane computes outputs {lane, +32, +64, +96}
        float acc[EQ][4];
#pragma unroll
        for (int k = 0; k < EQ; k++)
#pragma unroll
            for (int j = 0; j < 4; j++) acc[k][j] = 0.f;

#pragma unroll 4
        for (int i = 0; i < IN_DIM; i += 2) {
            float w00 = W1s[i * MSG_HID + lane];
            float w01 = W1s[i * MSG_HID + lane + 32];
            float w02 = W1s[i * MSG_HID + lane + 64];
            float w03 = W1s[i * MSG_HID + lane + 96];
            float w10 = W1s[(i + 1) * MSG_HID + lane];
            float w11 = W1s[(i + 1) * MSG_HID + lane + 32];
            float w12 = W1s[(i + 1) * MSG_HID + lane + 64];
            float w13 = W1s[(i + 1) * MSG_HID + lane + 96];
#pragma unroll
            for (int k = 0; k < EQ; k++) {
                float2 iv = *(const float2*)(win + k * IN_DIM + i);
                acc[k][0] += iv.x * w00 + iv.y * w10;
                acc[k][1] += iv.x * w01 + iv.y * w11;
                acc[k][2] += iv.x * w02 + iv.y * w12;
                acc[k][3] += iv.x * w03 + iv.y * w13;
            }
        }
#pragma unroll
        for (int k = 0; k < EQ; k++)
#pragma unroll
            for (int j = 0; j < 4; j++) {
                float h = acc[k][j] + b1s[lane + 32 * j];
                whid[k * MSG_HID + lane + 32 * j] = fmaxf(h, 0.f);
            }
        __syncwarp();

        // output layer: lane computes outputs {lane, lane+32}
        float acc2[EQ][2];
#pragma unroll
        for (int k = 0; k < EQ; k++) { acc2[k][0] = 0.f; acc2[k][1] = 0.f; }
#pragma unroll 4
        for (int i = 0; i < MSG_HID; i += 2) {
            float w00 = W2s[i * HID + lane];
            float w01 = W2s[i * HID + lane + 32];
            float w10 = W2s[(i + 1) * HID + lane];
            float w11 = W2s[(i + 1) * HID + lane + 32];
#pragma unroll
            for (int k = 0; k < EQ; k++) {
                float2 hv = *(const float2*)(whid + k * MSG_HID + i);
                acc2[k][0] += hv.x * w00 + hv.y * w10;
                acc2[k][1] += hv.x * w01 + hv.y * w11;
            }
        }
#pragma unroll
        for (int k = 0; k < EQ; k++) {
            atomicAdd(&g_m[d[k] * HID + lane], acc2[k][0] + b2s[lane]);
            atomicAdd(&g_m[d[k] * HID + lane + 32], acc2[k][1] + b2s[lane + 32]);
        }
        __syncwarp();
    }
}

// --------------------------------- GRU -------------------------------------
// gi = m @ Wih^T + bih ; gh = h @ Whh^T + bhh ; torch gate order (r,z,n)
#define GK_THREADS 256
#define GK_WARPS 8
#define NPW 2  // nodes per warp (weight reuse)
#define GRU_SMEM_FLOATS (2 * HID * 3 * HID * 2 /*WihT+WhhT*/ / 2 + 0)
// explicit: WihT 64*192 + WhhT 64*192 + bih 192 + bhh 192 + stage 8*NPW*128
#define GRU_SMEM_F (64 * 192 * 2 + 192 * 2 + GK_WARPS * NPW * 2 * HID)

__global__ __launch_bounds__(GK_THREADS, 2)
void gru_kernel(const float* __restrict__ Wih, const float* __restrict__ Whh,
                const float* __restrict__ bih, const float* __restrict__ bhh) {
    extern __shared__ float s[];
    float* WihT = s;                    // [c(64)][g(192)]
    float* WhhT = WihT + 64 * 192;
    float* bihs = WhhT + 64 * 192;      // 192
    float* bhhs = bihs + 192;           // 192
    float* stg  = bhhs + 192;           // [warp][NPW][128] (m row + h row)

    int tid = threadIdx.x;
    for (int idx = tid; idx < 192 * 64; idx += GK_THREADS) {
        int g = idx >> 6, c = idx & 63;
        WihT[c * 192 + g] = Wih[idx];
        WhhT[c * 192 + g] = Whh[idx];
    }
    for (int idx = tid; idx < 192; idx += GK_THREADS) {
        bihs[idx] = bih[idx];
        bhhs[idx] = bhh[idx];
    }
    __syncthreads();

    int warp = tid >> 5, lane = tid & 31;
    float* ws = stg + warp * NPW * 2 * HID;
    const int npairs = N_NODES / NPW;  // 25000 exactly

    for (int p = blockIdx.x * GK_WARPS + warp; p < npairs;
         p += gridDim.x * GK_WARPS) {
        int v0 = p * NPW;
#pragma unroll
        for (int n = 0; n < NPW; n++) {
            int v = v0 + n;
            ws[n * 128 + lane]      = g_m[v * HID + lane];
            ws[n * 128 + lane + 32] = g_m[v * HID + lane + 32];
            ws[n * 128 + 64 + lane]      = g_x[v * HID + lane];
            ws[n * 128 + 64 + lane + 32] = g_x[v * HID + lane + 32];
        }
        __syncwarp();

        float ai[NPW][6], ah[NPW][6];
#pragma unroll
        for (int n = 0; n < NPW; n++)
#pragma unroll
            for (int j = 0; j < 6; j++) { ai[n][j] = 0.f; ah[n][j] = 0.f; }

#pragma unroll 2
        for (int c = 0; c < HID; c++) {
            const float* wi = &WihT[c * 192 + lane];
            const float* wh = &WhhT[c * 192 + lane];
#pragma unroll
            for (int n = 0; n < NPW; n++) {
                float mv = ws[n * 128 + c];
                float hv = ws[n * 128 + 64 + c];
#pragma unroll
                for (int j = 0; j < 6; j++) {
                    ai[n][j] += mv * wi[32 * j];
                    ah[n][j] += hv * wh[32 * j];
                }
            }
        }
#pragma unroll
        for (int n = 0; n < NPW; n++) {
            int v = v0 + n;
#pragma unroll
            for (int j2 = 0; j2 < 2; j2++) {
                int ch = lane + 32 * j2;
                float r = sigmoidf_(ai[n][j2] + bihs[ch] + ah[n][j2] + bhhs[ch]);
                float z = sigmoidf_(ai[n][2 + j2] + bihs[64 + ch] +
                                    ah[n][2 + j2] + bhhs[64 + ch]);
                float nn = tanhf(ai[n][4 + j2] + bihs[128 + ch] +
                                 r * (ah[n][4 + j2] + bhhs[128 + ch]));
                float hold = ws[n * 128 + 64 + ch];
                g_x[v * HID + ch] = (1.f - z) * nn + z * hold;
            }
        }
        __syncwarp();
    }
}

// ------------------------------- LSTM cell ---------------------------------
// g = q_star @ Wih^T + bih + qh @ Whh^T + bhh ; torch gate order (i,f,g,o)
#define LSTM_SMEM_F (256 * 128 + 256 * 64 + 4 * 128 + 4 * 64)

__global__ __launch_bounds__(256, 1)
void lstm_kernel(const float* __restrict__ Wih, const float* __restrict__ Whh,
                 const float* __restrict__ bih, const float* __restrict__ bhh) {
    extern __shared__ float s[];
    float* WihT = s;                   // [c(128)][gate(256)]
    float* WhhT = WihT + 256 * 128;    // [c(64)][gate(256)]
    float* qs_s = WhhT + 256 * 64;     // [4][128]
    float* qh_s = qs_s + 4 * 128;      // [4][64]

    int tid = threadIdx.x;
    for (int idx = tid; idx < 256 * 128; idx += 256) {
        int g = idx >> 7, c = idx & 127;
        WihT[c * 256 + g] = Wih[idx];
    }
    for (int idx = tid; idx < 256 * 64; idx += 256) {
        int g = idx >> 6, c = idx & 63;
        WhhT[c * 256 + g] = Whh[idx];
    }
    int g0 = blockIdx.x * 4;
    for (int idx = tid; idx < 4 * 128; idx += 256)
        qs_s[idx] = g_qstar[g0 * 128 + idx];
    for (int idx = tid; idx < 4 * 64; idx += 256)
        qh_s[idx] = g_qh[g0 * 64 + idx];
    __syncthreads();

    int lg = tid >> 6;       // local graph 0..3
    int u = tid & 63;        // hidden unit
    int g = g0 + lg;
    float accI = bih[u] + bhh[u];
    float accF = bih[64 + u] + bhh[64 + u];
    float accG = bih[128 + u] + bhh[128 + u];
    float accO = bih[192 + u] + bhh[192 + u];
    const float* qs = qs_s + lg * 128;
#pragma unroll 4
    for (int c = 0; c < 128; c++) {
        float v = qs[c];
        const float* w = &WihT[c * 256];
        accI += v * w[u];
        accF += v * w[64 + u];
        accG += v * w[128 + u];
        accO += v * w[192 + u];
    }
    const float* qh = qh_s + lg * 64;
#pragma unroll 4
    for (int c = 0; c < 64; c++) {
        float v = qh[c];
        const float* w = &WhhT[c * 256];
        accI += v * w[u];
        accF += v * w[64 + u];
        accG += v * w[128 + u];
        accO += v * w[192 + u];
    }
    float i_ = sigmoidf_(accI), f_ = sigmoidf_(accF);
    float gg = tanhf(accG), o_ = sigmoidf_(accO);
    float c_new = f_ * g_qc[g * 64 + u] + i_ * gg;
    float h_new = o_ * tanhf(c_new);
    g_qc[g * 64 + u] = c_new;
    g_qh[g * 64 + u] = h_new;
}

// ----------------------------- attention steps -----------------------------
__global__ void attn_dot_kernel(const int* __restrict__ batch) {
    int wg = (blockIdx.x * blockDim.x + threadIdx.x) >> 5;
    int lane = threadIdx.x & 31;
    if (wg >= N_NODES) return;
    int v = wg;
    int b = batch[v];
    float p = g_x[v * HID + lane] * g_qh[b * HID + lane] +
              g_x[v * HID + lane + 32] * g_qh[b * HID + lane + 32];
#pragma unroll
    for (int o = 16; o; o >>= 1) p += __shfl_down_sync(0xffffffffu, p, o);
    if (lane == 0) {
        g_e[v] = p;
        atomicMax(&g_emax[b], enc_f(p));
    }
}

__global__ void attn_exp_kernel(const int* __restrict__ batch) {
    int v = blockIdx.x * blockDim.x + threadIdx.x;
    if (v >= N_NODES) return;
    int b = batch[v];
    float a = expf(g_e[v] - dec_f(g_emax[b]));
    g_a[v] = a;
    atomicAdd(&g_asum[b], a);
}

__global__ void attn_rvec_kernel(const int* __restrict__ batch) {
    int wg = (blockIdx.x * blockDim.x + threadIdx.x) >> 5;
    int lane = threadIdx.x & 31;
    if (wg >= N_NODES) return;
    int v = wg;
    int b = batch[v];
    float coef = g_a[v] / g_asum[b];
    atomicAdd(&g_rvec[b * HID + lane], coef * g_x[v * HID + lane]);
    atomicAdd(&g_rvec[b * HID + lane + 32], coef * g_x[v * HID + lane + 32]);
}

__global__ void qstar_kernel() {
    int t = blockIdx.x * blockDim.x + threadIdx.x;
    if (t >= NUM_GRAPHS * HID) return;
    int g = t >> 6, u = t & 63;
    g_qstar[g * 2 * HID + u] = g_qh[t];
    g_qstar[g * 2 * HID + HID + u] = g_rvec[t];
}

// ------------------------------- regressor ---------------------------------
__global__ void reg_kernel(const float* __restrict__ W1,
                           const float* __restrict__ b1,
                           const float* __restrict__ W2,
                           const float* __restrict__ b2,
                           float* __restrict__ out) {
    __shared__ float qs[128];
    __shared__ float red[64];
    int g = blockIdx.x;
    int u = threadIdx.x;  // 64 threads
    qs[u] = g_qstar[g * 128 + u];
    qs[u + 64] = g_qstar[g * 128 + u + 64];
    __syncthreads();
    float acc = b1[u];
#pragma unroll 4
    for (int c = 0; c < 128; c++) acc += qs[c] * W1[c * HID + u];
    red[u] = fmaxf(acc, 0.f) * W2[u];
    __syncthreads();
    for (int sft = 32; sft; sft >>= 1) {
        if (u < sft) red[u] += red[u + sft];
        __syncthreads();
    }
    if (u == 0) out[g] = red[0] + b2[0];
}

// ------------------------------ host driver --------------------------------
extern "C" void kernel_launch(void* const* d_in, const int* in_sizes, int n_in,
                              void* d_out, int out_size) {
    const float* x_feat     = (const float*)d_in[0];
    const int*   edge_index = (const int*)d_in[1];
    const float* edge_attr  = (const float*)d_in[2];
    const int*   batch      = (const int*)d_in[3];
    const float* W_emb = (const float*)d_in[4];
    const float* b_emb = (const float*)d_in[5];
    const float* W_m1  = (const float*)d_in[6];
    const float* b_m1  = (const float*)d_in[7];
    const float* W_m2  = (const float*)d_in[8];
    const float* b_m2  = (const float*)d_in[9];
    const float* gWih  = (const float*)d_in[10];
    const float* gWhh  = (const float*)d_in[11];
    const float* gbih  = (const float*)d_in[12];
    const float* gbhh  = (const float*)d_in[13];
    const float* lWih  = (const float*)d_in[14];
    const float* lWhh  = (const float*)d_in[15];
    const float* lbih  = (const float*)d_in[16];
    const float* lbhh  = (const float*)d_in[17];
    const float* Wr1   = (const float*)d_in[18];
    const float* br1   = (const float*)d_in[19];
    const float* Wr2   = (const float*)d_in[20];
    const float* br2   = (const float*)d_in[21];
    float* out = (float*)d_out;

    const int ek_smem   = EK_SMEM_FLOATS * (int)sizeof(float);
    const int gru_smem  = GRU_SMEM_F * (int)sizeof(float);
    const int lstm_smem = LSTM_SMEM_F * (int)sizeof(float);
    cudaFuncSetAttribute(edge_msg_kernel,
                         cudaFuncAttributeMaxDynamicSharedMemorySize, ek_smem);
    cudaFuncSetAttribute(gru_kernel,
                         cudaFuncAttributeMaxDynamicSharedMemorySize, gru_smem);
    cudaFuncSetAttribute(lstm_kernel,
                         cudaFuncAttributeMaxDynamicSharedMemorySize, lstm_smem);

    // 1. node embedding
    embed_kernel<<<(N_NODES * HID + 255) / 256, 256>>>(x_feat, W_emb, b_emb);

    // 2. message passing rounds
    for (int r = 0; r < NUM_MP; r++) {
        zero_m_kernel<<<(N_NODES * HID + 255) / 256, 256>>>();
        edge_msg_kernel<<<148, EK_THREADS, ek_smem>>>(edge_index, edge_attr,
                                                      W_m1, b_m1, W_m2, b_m2);
        gru_kernel<<<296, GK_THREADS, gru_smem>>>(gWih, gWhh, gbih, gbhh);
    }

    // 3. Set2Set
    zero_s2s_state_kernel<<<(NUM_GRAPHS * 2 * HID + 255) / 256, 256>>>();
    for (int s = 0; s < S2S_STEPS; s++) {
        lstm_kernel<<<NUM_GRAPHS / 4, 256, lstm_smem>>>(lWih, lWhh, lbih, lbhh);
        zero_attn_kernel<<<(NUM_GRAPHS * HID + 255) / 256, 256>>>();
        attn_dot_kernel<<<(N_NODES * 32 + 255) / 256, 256>>>(batch);
        attn_exp_kernel<<<(N_NODES + 255) / 256, 256>>>(batch);
        attn_rvec_kernel<<<(N_NODES * 32 + 255) / 256, 256>>>(batch);
        qstar_kernel<<<(NUM_GRAPHS * HID + 255) / 256, 256>>>();
    }

    // 4. regressor
    reg_kernel<<<NUM_GRAPHS, 64>>>(Wr1, br1, Wr2, br2, out);
    (void)in_sizes; (void)n_in; (void)out_size;
}

// round 2
// speedup vs baseline: 1.0039x; 1.0039x over previous
#include <cuda_runtime.h>

// ---------------------------------------------------------------------------
// MPNN forward (embed -> 3x [edge MLP msg + scatter-add + GRU] -> Set2Set(6) ->
// regressor), all fp32, graph-capturable, allocation-free.
// ---------------------------------------------------------------------------

#define N_NODES 50000
#define N_EDGES 800000
#define NODE_DIM 32
#define EDGE_DIM 16
#define HID 64
#define MSG_HID 128
#define NUM_GRAPHS 512
#define NUM_MP 3
#define S2S_STEPS 6
#define IN_DIM (2 * HID + EDGE_DIM)  // 144

// ------------------------- scratch (device globals) ------------------------
__device__ float g_x[N_NODES * HID];        // node state (x == h)
__device__ float g_m[N_NODES * HID];        // aggregated messages
__device__ float g_qh[NUM_GRAPHS * HID];
__device__ float g_qc[NUM_GRAPHS * HID];
__device__ float g_qstar[NUM_GRAPHS * 2 * HID];
__device__ float g_e[N_NODES];
__device__ float g_a[N_NODES];
__device__ unsigned g_emax[NUM_GRAPHS];     // order-encoded float max
__device__ float g_asum[NUM_GRAPHS];
__device__ float g_rvec[NUM_GRAPHS * HID];

__device__ __forceinline__ float sigmoidf_(float x) { return 1.f / (1.f + expf(-x)); }

// monotone float <-> uint encoding for atomicMax
__device__ __forceinline__ unsigned enc_f(float f) {
    unsigned u = __float_as_uint(f);
    return (u & 0x80000000u) ? ~u : (u | 0x80000000u);
}
__device__ __forceinline__ float dec_f(unsigned k) {
    return (k & 0x80000000u) ? __uint_as_float(k & 0x7fffffffu)
                             : __uint_as_float(~k);
}

// ------------------------------ zero kernels -------------------------------
__global__ void zero_m_kernel() {
    int t = blockIdx.x * blockDim.x + threadIdx.x;
    if (t < N_NODES * HID) g_m[t] = 0.f;
}
__global__ void zero_s2s_state_kernel() {
    int t = blockIdx.x * blockDim.x + threadIdx.x;
    if (t < NUM_GRAPHS * HID) { g_qh[t] = 0.f; g_qc[t] = 0.f; }
    if (t < NUM_GRAPHS * 2 * HID) g_qstar[t] = 0.f;
}
__global__ void zero_attn_kernel() {
    int t = blockIdx.x * blockDim.x + threadIdx.x;
    if (t < NUM_GRAPHS) { g_emax[t] = 0u; g_asum[t] = 0.f; }
    if (t < NUM_GRAPHS * HID) g_rvec[t] = 0.f;
}

// ------------------------------- embedding ---------------------------------
__global__ void embed_kernel(const float* __restrict__ xf,
                             const float* __restrict__ W,
                             const float* __restrict__ b) {
    int t = blockIdx.x * blockDim.x + threadIdx.x;
    if (t >= N_NODES * HID) return;
    int v = t >> 6, o = t & 63;
    const float* xr = xf + v * NODE_DIM;
    float acc = b[o];
#pragma unroll
    for (int c = 0; c < NODE_DIM; c++) acc += xr[c] * W[c * HID + o];
    g_x[t] = acc;
}

// ------------------------- edge message MLP kernel -------------------------
// Per warp: EQ edges at a time (weight reuse x EQ). Weights resident in smem.
#define EK_THREADS 512
#define EK_WARPS 16
#define EQ 4
#define EK_SMEM_FLOATS (IN_DIM * MSG_HID + MSG_HID + MSG_HID * HID + HID + \
                        EK_WARPS * EQ * IN_DIM + EK_WARPS * EQ * MSG_HID)

__global__ __launch_bounds__(EK_THREADS, 1)
void edge_msg_kernel(const int* __restrict__ ei, const float* __restrict__ ea,
                     const float* __restrict__ W1, const float* __restrict__ b1,
                     const float* __restrict__ W2, const float* __restrict__ b2) {
    extern __shared__ float smem[];
    float* W1s  = smem;                              // 144*128
    float* b1s  = W1s + IN_DIM * MSG_HID;            // 128
    float* W2s  = b1s + MSG_HID;                     // 128*64
    float* b2s  = W2s + MSG_HID * HID;               // 64
    float* in_s = b2s + HID;                         // EK_WARPS*EQ*144
    float* hid_s = in_s + EK_WARPS * EQ * IN_DIM;    // EK_WARPS*EQ*128

    int tid = threadIdx.x;
    for (int i = tid; i < IN_DIM * MSG_HID; i += EK_THREADS) W1s[i] = W1[i];
    for (int i = tid; i < MSG_HID; i += EK_THREADS) b1s[i] = b1[i];
    for (int i = tid; i < MSG_HID * HID; i += EK_THREADS) W2s[i] = W2[i];
    for (int i = tid; i < HID; i += EK_THREADS) b2s[i] = b2[i];
    __syncthreads();

    int warp = tid >> 5, lane = tid & 31;
    float* win  = in_s + warp * EQ * IN_DIM;
    float* whid = hid_s + warp * EQ * MSG_HID;
    const int* src = ei;
    const int* dst = ei + N_EDGES;

    const int nquads = N_EDGES / EQ;
    for (int q = blockIdx.x * EK_WARPS + warp; q < nquads;
         q += gridDim.x * EK_WARPS) {
        int e0 = q * EQ;
        int d[EQ];
        // stage inputs: [x[dst](64) | x[src](64) | edge_attr(16)]
#pragma unroll
        for (int k = 0; k < EQ; k++) {
            int e = e0 + k;
            int s = src[e];
            int dd = dst[e];
            d[k] = dd;
            const float* xd = g_x + dd * HID;
            const float* xs = g_x + s * HID;
#pragma unroll
            for (int j = 0; j < 5; j++) {
                int idx = lane + 32 * j;
                if (idx < IN_DIM) {
                    float v;
                    if (idx < HID) v = xd[idx];
                    else if (idx < 2 * HID) v = xs[idx - HID];
                    else v = ea[e * EDGE_DIM + (idx - 2 * HID)];
                    win[k * IN_DIM + idx] = v;
                }
            }
        }
        __syncwarp();

        // hidden layer: lane computes outputs {lane, +32, +64, +96}
        float acc[EQ][4];
#pragma unroll
        for (int k = 0; k < EQ; k++)
#pragma unroll
            for (int j = 0; j < 4; j++) acc[k][j] = 0.f;

#pragma unroll 4
        for (int i = 0; i < IN_DIM; i += 2) {
            float w00 = W1s[i * MSG_HID + lane];
            float w01 = W1s[i * MSG_HID + lane + 32];
            float w02 = W1s[i * MSG_HID + lane + 64];
            float w03 = W1s[i * MSG_HID + lane + 96];
            float w10 = W1s[(i + 1) * MSG_HID + lane];
            float w11 = W1s[(i + 1) * MSG_HID + lane + 32];
            float w12 = W1s[(i + 1) * MSG_HID + lane + 64];
            float w13 = W1s[(i + 1) * MSG_HID + lane + 96];
#pragma unroll
            for (int k = 0; k < EQ; k++) {
                float2 iv = *(const float2*)(win + k * IN_DIM + i);
                acc[k][0] += iv.x * w00 + iv.y * w10;
                acc[k][1] += iv.x * w01 + iv.y * w11;
                acc[k][2] += iv.x * w02 + iv.y * w12;
                acc[k][3] += iv.x * w03 + iv.y * w13;
            }
        }
#pragma unroll
        for (int k = 0; k < EQ; k++)
#pragma unroll
            for (int j = 0; j < 4; j++) {
                float h = acc[k][j] + b1s[lane + 32 * j];
                whid[k * MSG_HID + lane + 32 * j] = fmaxf(h, 0.f);
            }
        __syncwarp();

        // output layer: lane computes outputs {lane, lane+32}
        float acc2[EQ][2];
#pragma unroll
        for (int k = 0; k < EQ; k++) { acc2[k][0] = 0.f; acc2[k][1] = 0.f; }
#pragma unroll 4
        for (int i = 0; i < MSG_HID; i += 2) {
            float w00 = W2s[i * HID + lane];
            float w01 = W2s[i * HID + lane + 32];
            float w10 = W2s[(i + 1) * HID + lane];
            float w11 = W2s[(i + 1) * HID + lane + 32];
#pragma unroll
            for (int k = 0; k < EQ; k++) {
                float2 hv = *(const float2*)(whid + k * MSG_HID + i);
                acc2[k][0] += hv.x * w00 + hv.y * w10;
                acc2[k][1] += hv.x * w01 + hv.y * w11;
            }
        }
#pragma unroll
        for (int k = 0; k < EQ; k++) {
            atomicAdd(&g_m[d[k] * HID + lane], acc2[k][0] + b2s[lane]);
            atomicAdd(&g_m[d[k] * HID + lane + 32], acc2[k][1] + b2s[lane + 32]);
        }
        __syncwarp();
    }
}

// --------------------------------- GRU -------------------------------------
// gi = m @ Wih^T + bih ; gh = h @ Whh^T + bhh ; torch gate order (r,z,n)
#define GK_THREADS 256
#define GK_WARPS 8
#define NPW 2  // nodes per warp (weight reuse)
#define GRU_SMEM_FLOATS (2 * HID * 3 * HID * 2 /*WihT+WhhT*/ / 2 + 0)
// explicit: WihT 64*192 + WhhT 64*192 + bih 192 + bhh 192 + stage 8*NPW*128
#define GRU_SMEM_F (64 * 192 * 2 + 192 * 2 + GK_WARPS * NPW * 2 * HID)

__global__ __launch_bounds__(GK_THREADS, 2)
void gru_kernel(const float* __restrict__ Wih, const float* __restrict__ Whh,
                const float* __restrict__ bih, const float* __restrict__ bhh) {
    extern __shared__ float s[];
    float* WihT = s;                    // [c(64)][g(192)]
    float* WhhT = WihT + 64 * 192;
    float* bihs = WhhT + 64 * 192;      // 192
    float* bhhs = bihs + 192;           // 192
    float* stg  = bhhs + 192;           // [warp][NPW][128] (m row + h row)

    int tid = threadIdx.x;
    for (int idx = tid; idx < 192 * 64; idx += GK_THREADS) {
        int g = idx >> 6, c = idx & 63;
        WihT[c * 192 + g] = Wih[idx];
        WhhT[c * 192 + g] = Whh[idx];
    }
    for (int idx = tid; idx < 192; idx += GK_THREADS) {
        bihs[idx] = bih[idx];
        bhhs[idx] = bhh[idx];
    }
    __syncthreads();

    int warp = tid >> 5, lane = tid & 31;
    float* ws = stg + warp * NPW * 2 * HID;
    const int npairs = N_NODES / NPW;  // 25000 exactly

    for (int p = blockIdx.x * GK_WARPS + warp; p < npairs;
         p += gridDim.x * GK_WARPS) {
        int v0 = p * NPW;
#pragma unroll
        for (int n = 0; n < NPW; n++) {
            int v = v0 + n;
            ws[n * 128 + lane]      = g_m[v * HID + lane];
            ws[n * 128 + lane + 32] = g_m[v * HID + lane + 32];
            ws[n * 128 + 64 + lane]      = g_x[v * HID + lane];
            ws[n * 128 + 64 + lane + 32] = g_x[v * HID + lane + 32];
        }
        __syncwarp();

        float ai[NPW][6], ah[NPW][6];
#pragma unroll
        for (int n = 0; n < NPW; n++)
#pragma unroll
            for (int j = 0; j < 6; j++) { ai[n][j] = 0.f; ah[n][j] = 0.f; }

#pragma unroll 2
        for (int c = 0; c < HID; c++) {
            const float* wi = &WihT[c * 192 + lane];
            const float* wh = &WhhT[c * 192 + lane];
#pragma unroll
            for (int n = 0; n < NPW; n++) {
                float mv = ws[n * 128 + c];
                float hv = ws[n * 128 + 64 + c];
#pragma unroll
                for (int j = 0; j < 6; j++) {
                    ai[n][j] += mv * wi[32 * j];
                    ah[n][j] += hv * wh[32 * j];
                }
            }
        }
#pragma unroll
        for (int n = 0; n < NPW; n++) {
            int v = v0 + n;
#pragma unroll
            for (int j2 = 0; j2 < 2; j2++) {
                int ch = lane + 32 * j2;
                float r = sigmoidf_(ai[n][j2] + bihs[ch] + ah[n][j2] + bhhs[ch]);
                float z = sigmoidf_(ai[n][2 + j2] + bihs[64 + ch] +
                                    ah[n][2 + j2] + bhhs[64 + ch]);
                float nn = tanhf(ai[n][4 + j2] + bihs[128 + ch] +
                                 r * (ah[n][4 + j2] + bhhs[128 + ch]));
                float hold = ws[n * 128 + 64 + ch];
                g_x[v * HID + ch] = (1.f - z) * nn + z * hold;
            }
        }
        __syncwarp();
    }
}

// ------------------------------- LSTM cell ---------------------------------
// g = q_star @ Wih^T + bih + qh @ Whh^T + bhh ; torch gate order (i,f,g,o)
#define LSTM_SMEM_F (256 * 128 + 256 * 64 + 4 * 128 + 4 * 64)

__global__ __launch_bounds__(256, 1)
void lstm_kernel(const float* __restrict__ Wih, const float* __restrict__ Whh,
                 const float* __restrict__ bih, const float* __restrict__ bhh) {
    extern __shared__ float s[];
    float* WihT = s;                   // [c(128)][gate(256)]
    float* WhhT = WihT + 256 * 128;    // [c(64)][gate(256)]
    float* qs_s = WhhT + 256 * 64;     // [4][128]
    float* qh_s = qs_s + 4 * 128;      // [4][64]

    int tid = threadIdx.x;
    for (int idx = tid; idx < 256 * 128; idx += 256) {
        int g = idx >> 7, c = idx & 127;
        WihT[c * 256 + g] = Wih[idx];
    }
    for (int idx = tid; idx < 256 * 64; idx += 256) {
        int g = idx >> 6, c = idx & 63;
        WhhT[c * 256 + g] = Whh[idx];
    }
    int g0 = blockIdx.x * 4;
    for (int idx = tid; idx < 4 * 128; idx += 256)
        qs_s[idx] = g_qstar[g0 * 128 + idx];
    for (int idx = tid; idx < 4 * 64; idx += 256)
        qh_s[idx] = g_qh[g0 * 64 + idx];
    __syncthreads();

    int lg = tid >> 6;       // local graph 0..3
    int u = tid & 63;        // hidden unit
    int g = g0 + lg;
    float accI = bih[u] + bhh[u];
    float accF = bih[64 + u] + bhh[64 + u];
    float accG = bih[128 + u] + bhh[128 + u];
    float accO = bih[192 + u] + bhh[192 + u];
    const float* qs = qs_s + lg * 128;
#pragma unroll 4
    for (int c = 0; c < 128; c++) {
        float v = qs[c];
        const float* w = &WihT[c * 256];
        accI += v * w[u];
        accF += v * w[64 + u];
        accG += v * w[128 + u];
        accO += v * w[192 + u];
    }
    const float* qh = qh_s + lg * 64;
#pragma unroll 4
    for (int c = 0; c < 64; c++) {
        float v = qh[c];
        const float* w = &WhhT[c * 256];
        accI += v * w[u];
        accF += v * w[64 + u];
        accG += v * w[128 + u];
        accO += v * w[192 + u];
    }
    float i_ = sigmoidf_(accI), f_ = sigmoidf_(accF);
    float gg = tanhf(accG), o_ = sigmoidf_(accO);
    float c_new = f_ * g_qc[g * 64 + u] + i_ * gg;
    float h_new = o_ * tanhf(c_new);
    g_qc[g * 64 + u] = c_new;
    g_qh[g * 64 + u] = h_new;
}

// ----------------------------- attention steps -----------------------------
__global__ void attn_dot_kernel(const int* __restrict__ batch) {
    int wg = (blockIdx.x * blockDim.x + threadIdx.x) >> 5;
    int lane = threadIdx.x & 31;
    if (wg >= N_NODES) return;
    int v = wg;
    int b = batch[v];
    float p = g_x[v * HID + lane] * g_qh[b * HID + lane] +
              g_x[v * HID + lane + 32] * g_qh[b * HID + lane + 32];
#pragma unroll
    for (int o = 16; o; o >>= 1) p += __shfl_down_sync(0xffffffffu, p, o);
    if (lane == 0) {
        g_e[v] = p;
        atomicMax(&g_emax[b], enc_f(p));
    }
}

__global__ void attn_exp_kernel(const int* __restrict__ batch) {
    int v = blockIdx.x * blockDim.x + threadIdx.x;
    if (v >= N_NODES) return;
    int b = batch[v];
    float a = expf(g_e[v] - dec_f(g_emax[b]));
    g_a[v] = a;
    atomicAdd(&g_asum[b], a);
}

__global__ void attn_rvec_kernel(const int* __restrict__ batch) {
    int wg = (blockIdx.x * blockDim.x + threadIdx.x) >> 5;
    int lane = threadIdx.x & 31;
    if (wg >= N_NODES) return;
    int v = wg;
    int b = batch[v];
    float coef = g_a[v] / g_asum[b];
    atomicAdd(&g_rvec[b * HID + lane], coef * g_x[v * HID + lane]);
    atomicAdd(&g_rvec[b * HID + lane + 32], coef * g_x[v * HID + lane + 32]);
}

__global__ void qstar_kernel() {
    int t = blockIdx.x * blockDim.x + threadIdx.x;
    if (t >= NUM_GRAPHS * HID) return;
    int g = t >> 6, u = t & 63;
    g_qstar[g * 2 * HID + u] = g_qh[t];
    g_qstar[g * 2 * HID + HID + u] = g_rvec[t];
}

// ------------------------------- regressor ---------------------------------
__global__ void reg_kernel(const float* __restrict__ W1,
                           const float* __restrict__ b1,
                           const float* __restrict__ W2,
                           const float* __restrict__ b2,
                           float* __restrict__ out) {
    __shared__ float qs[128];
    __shared__ float red[64];
    int g = blockIdx.x;
    int u = threadIdx.x;  // 64 threads
    qs[u] = g_qstar[g * 128 + u];
    qs[u + 64] = g_qstar[g * 128 + u + 64];
    __syncthreads();
    float acc = b1[u];
#pragma unroll 4
    for (int c = 0; c < 128; c++) acc += qs[c] * W1[c * HID + u];
    red[u] = fmaxf(acc, 0.f) * W2[u];
    __syncthreads();
    for (int sft = 32; sft; sft >>= 1) {
        if (u < sft) red[u] += red[u + sft];
        __syncthreads();
    }
    if (u == 0) out[g] = red[0] + b2[0];
}

// ------------------------------ host driver --------------------------------
extern "C" void kernel_launch(void* const* d_in, const int* in_sizes, int n_in,
                              void* d_out, int out_size) {
    const float* x_feat     = (const float*)d_in[0];
    const int*   edge_index = (const int*)d_in[1];
    const float* edge_attr  = (const float*)d_in[2];
    const int*   batch      = (const int*)d_in[3];
    const float* W_emb = (const float*)d_in[4];
    const float* b_emb = (const float*)d_in[5];
    const float* W_m1  = (const float*)d_in[6];
    const float* b_m1  = (const float*)d_in[7];
    const float* W_m2  = (const float*)d_in[8];
    const float* b_m2  = (const float*)d_in[9];
    const float* gWih  = (const float*)d_in[10];
    const float* gWhh  = (const float*)d_in[11];
    const float* gbih  = (const float*)d_in[12];
    const float* gbhh  = (const float*)d_in[13];
    const float* lWih  = (const float*)d_in[14];
    const float* lWhh  = (const float*)d_in[15];
    const float* lbih  = (const float*)d_in[16];
    const float* lbhh  = (const float*)d_in[17];
    const float* Wr1   = (const float*)d_in[18];
    const float* br1   = (const float*)d_in[19];
    const float* Wr2   = (const float*)d_in[20];
    const float* br2   = (const float*)d_in[21];
    float* out = (float*)d_out;

    const int ek_smem   = EK_SMEM_FLOATS * (int)sizeof(float);
    const int gru_smem  = GRU_SMEM_F * (int)sizeof(float);
    const int lstm_smem = LSTM_SMEM_F * (int)sizeof(float);
    cudaFuncSetAttribute(edge_msg_kernel,
                         cudaFuncAttributeMaxDynamicSharedMemorySize, ek_smem);
    cudaFuncSetAttribute(gru_kernel,
                         cudaFuncAttributeMaxDynamicSharedMemorySize, gru_smem);
    cudaFuncSetAttribute(lstm_kernel,
                         cudaFuncAttributeMaxDynamicSharedMemorySize, lstm_smem);

    // 1. node embedding
    embed_kernel<<<(N_NODES * HID + 255) / 256, 256>>>(x_feat, W_emb, b_emb);

    // 2. message passing rounds
    for (int r = 0; r < NUM_MP; r++) {
        zero_m_kernel<<<(N_NODES * HID + 255) / 256, 256>>>();
        edge_msg_kernel<<<148, EK_THREADS, ek_smem>>>(edge_index, edge_attr,
                                                      W_m1, b_m1, W_m2, b_m2);
        gru_kernel<<<296, GK_THREADS, gru_smem>>>(gWih, gWhh, gbih, gbhh);
    }

    // 3. Set2Set
    zero_s2s_state_kernel<<<(NUM_GRAPHS * 2 * HID + 255) / 256, 256>>>();
    for (int s = 0; s < S2S_STEPS; s++) {
        lstm_kernel<<<NUM_GRAPHS / 4, 256, lstm_smem>>>(lWih, lWhh, lbih, lbhh);
        zero_attn_kernel<<<(NUM_GRAPHS * HID + 255) / 256, 256>>>();
        attn_dot_kernel<<<(N_NODES * 32 + 255) / 256, 256>>>(batch);
        attn_exp_kernel<<<(N_NODES + 255) / 256, 256>>>(batch);
        attn_rvec_kernel<<<(N_NODES * 32 + 255) / 256, 256>>>(batch);
        qstar_kernel<<<(NUM_GRAPHS * HID + 255) / 256, 256>>>();
    }

    // 4. regressor
    reg_kernel<<<NUM_GRAPHS, 64>>>(Wr1, br1, Wr2, br2, out);
    (void)in_sizes; (void)n_in; (void)out_size;
}

// round 3
// speedup vs baseline: 1.1871x; 1.1825x over previous
#include <cuda_runtime.h>

// ---------------------------------------------------------------------------
// MPNN forward (embed -> 3x [edge MLP msg + scatter-add + GRU] -> Set2Set(6) ->
// regressor), fp32, graph-capturable, allocation-free.
// R2: edge MLP uses packed fma.rn.f32x2 (FFMA2) — two edges per SIMD pair.
// ---------------------------------------------------------------------------

#define N_NODES 50000
#define N_EDGES 800000
#define NODE_DIM 32
#define EDGE_DIM 16
#define HID 64
#define MSG_HID 128
#define NUM_GRAPHS 512
#define NUM_MP 3
#define S2S_STEPS 6
#define IN_DIM (2 * HID + EDGE_DIM)  // 144

// ------------------------- scratch (device globals) ------------------------
__device__ float g_x[N_NODES * HID];        // node state (x == h)
__device__ float g_m[N_NODES * HID];        // aggregated messages
__device__ float g_qh[NUM_GRAPHS * HID];
__device__ float g_qc[NUM_GRAPHS * HID];
__device__ float g_qstar[NUM_GRAPHS * 2 * HID];
__device__ float g_e[N_NODES];
__device__ float g_a[N_NODES];
__device__ unsigned g_emax[NUM_GRAPHS];     // order-encoded float max
__device__ float g_asum[NUM_GRAPHS];
__device__ float g_rvec[NUM_GRAPHS * HID];

__device__ __forceinline__ float sigmoidf_(float x) { return 1.f / (1.f + expf(-x)); }

__device__ __forceinline__ unsigned enc_f(float f) {
    unsigned u = __float_as_uint(f);
    return (u & 0x80000000u) ? ~u : (u | 0x80000000u);
}
__device__ __forceinline__ float dec_f(unsigned k) {
    return (k & 0x80000000u) ? __uint_as_float(k & 0x7fffffffu)
                             : __uint_as_float(~k);
}

// ----------------------- packed f32x2 helpers (sm_100+) --------------------
__device__ __forceinline__ unsigned long long fma2(unsigned long long a,
                                                   unsigned long long b,
                                                   unsigned long long c) {
    unsigned long long d;
    asm("fma.rn.f32x2 %0, %1, %2, %3;" : "=l"(d) : "l"(a), "l"(b), "l"(c));
    return d;
}
__device__ __forceinline__ unsigned long long dup2(float x) {
    unsigned long long d;
    asm("mov.b64 %0, {%1, %1};" : "=l"(d) : "f"(x));
    return d;
}
__device__ __forceinline__ float2 unpk(unsigned long long v) {
    float lo, hi;
    asm("mov.b64 {%0, %1}, %2;" : "=f"(lo), "=f"(hi) : "l"(v));
    return make_float2(lo, hi);
}

// ------------------------------ zero kernels -------------------------------
__global__ void zero_m_kernel() {
    int t = blockIdx.x * blockDim.x + threadIdx.x;
    if (t < N_NODES * HID) g_m[t] = 0.f;
}
__global__ void zero_s2s_state_kernel() {
    int t = blockIdx.x * blockDim.x + threadIdx.x;
    if (t < NUM_GRAPHS * HID) { g_qh[t] = 0.f; g_qc[t] = 0.f; }
    if (t < NUM_GRAPHS * 2 * HID) g_qstar[t] = 0.f;
}
__global__ void zero_attn_kernel() {
    int t = blockIdx.x * blockDim.x + threadIdx.x;
    if (t < NUM_GRAPHS) { g_emax[t] = 0u; g_asum[t] = 0.f; }
    if (t < NUM_GRAPHS * HID) g_rvec[t] = 0.f;
}

// ------------------------------- embedding ---------------------------------
__global__ void embed_kernel(const float* __restrict__ xf,
                             const float* __restrict__ W,
                             const float* __restrict__ b) {
    int t = blockIdx.x * blockDim.x + threadIdx.x;
    if (t >= N_NODES * HID) return;
    int v = t >> 6, o = t & 63;
    const float* xr = xf + v * NODE_DIM;
    float acc = b[o];
#pragma unroll
    for (int c = 0; c < NODE_DIM; c++) acc += xr[c] * W[c * HID + o];
    g_x[t] = acc;
}

// ------------------------- edge message MLP kernel -------------------------
// Per warp: 4 edges at a time, packed 2-per-f32x2. Channel-major staging with
// row stride 6 floats (4 edges + 2 pad) so an 8B broadcast LDS yields an
// edge-pair operand directly.
#define EK_THREADS 512
#define EK_WARPS 16
#define EQ 4
#define IN_STRIDE 6   // floats per staged input row
#define EK_SMEM_FLOATS (IN_DIM * MSG_HID + MSG_HID + MSG_HID * HID + HID + \
                        EK_WARPS * (IN_DIM * IN_STRIDE + MSG_HID * IN_STRIDE))

__global__ __launch_bounds__(EK_THREADS, 1)
void edge_msg_kernel(const int* __restrict__ ei, const float* __restrict__ ea,
                     const float* __restrict__ W1, const float* __restrict__ b1,
                     const float* __restrict__ W2, const float* __restrict__ b2) {
    extern __shared__ float smem[];
    float* W1s  = smem;                              // 144*128
    float* b1s  = W1s + IN_DIM * MSG_HID;            // 128
    float* W2s  = b1s + MSG_HID;                     // 128*64
    float* b2s  = W2s + MSG_HID * HID;               // 64
    float* in_s = b2s + HID;                         // warps * 144*6
    float* hid_s = in_s + EK_WARPS * IN_DIM * IN_STRIDE;  // warps * 128*6

    int tid = threadIdx.x;
    for (int i = tid; i < IN_DIM * MSG_HID; i += EK_THREADS) W1s[i] = W1[i];
    for (int i = tid; i < MSG_HID; i += EK_THREADS) b1s[i] = b1[i];
    for (int i = tid; i < MSG_HID * HID; i += EK_THREADS) W2s[i] = W2[i];
    for (int i = tid; i < HID; i += EK_THREADS) b2s[i] = b2[i];
    __syncthreads();

    int warp = tid >> 5, lane = tid & 31;
    float* win  = in_s + warp * IN_DIM * IN_STRIDE;
    float* whid = hid_s + warp * MSG_HID * IN_STRIDE;
    const int* src = ei;
    const int* dst = ei + N_EDGES;

    const int nquads = N_EDGES / EQ;
    for (int q = blockIdx.x * EK_WARPS + warp; q < nquads;
         q += gridDim.x * EK_WARPS) {
        int e0 = q * EQ;
        int d[EQ];
        // stage inputs channel-major: win[idx*6 + k] = feature idx of edge k
#pragma unroll
        for (int k = 0; k < EQ; k++) {
            int e = e0 + k;
            int s = src[e];
            int dd = dst[e];
            d[k] = dd;
            const float* xd = g_x + dd * HID;
            const float* xs = g_x + s * HID;
#pragma unroll
            for (int j = 0; j < 5; j++) {
                int idx = lane + 32 * j;
                if (idx < IN_DIM) {
                    float v;
                    if (idx < HID) v = xd[idx];
                    else if (idx < 2 * HID) v = xs[idx - HID];
                    else v = ea[e * EDGE_DIM + (idx - 2 * HID)];
                    win[idx * IN_STRIDE + k] = v;
                }
            }
        }
        __syncwarp();

        // hidden layer: lane computes outputs {lane,+32,+64,+96} for 4 edges,
        // packed as 2 edge-pairs.
        unsigned long long acc[4][2];
#pragma unroll
        for (int j = 0; j < 4; j++) { acc[j][0] = 0ull; acc[j][1] = 0ull; }

#pragma unroll 4
        for (int i = 0; i < IN_DIM; i++) {
            unsigned long long in0 = *(const unsigned long long*)(win + i * IN_STRIDE);
            unsigned long long in1 = *(const unsigned long long*)(win + i * IN_STRIDE + 2);
            const float* wr = W1s + i * MSG_HID + lane;
#pragma unroll
            for (int j = 0; j < 4; j++) {
                unsigned long long w = dup2(wr[32 * j]);
                acc[j][0] = fma2(w, in0, acc[j][0]);
                acc[j][1] = fma2(w, in1, acc[j][1]);
            }
        }
#pragma unroll
        for (int j = 0; j < 4; j++) {
            int ch = lane + 32 * j;
            float b = b1s[ch];
            float2 f0 = unpk(acc[j][0]);
            float2 f1 = unpk(acc[j][1]);
            *(float2*)(whid + ch * IN_STRIDE) =
                make_float2(fmaxf(f0.x + b, 0.f), fmaxf(f0.y + b, 0.f));
            *(float2*)(whid + ch * IN_STRIDE + 2) =
                make_float2(fmaxf(f1.x + b, 0.f), fmaxf(f1.y + b, 0.f));
        }
        __syncwarp();

        // output layer: lane computes outputs {lane, lane+32} for 4 edges
        unsigned long long acc2[2][2];
        acc2[0][0] = acc2[0][1] = acc2[1][0] = acc2[1][1] = 0ull;
#pragma unroll 4
        for (int i = 0; i < MSG_HID; i++) {
            unsigned long long h0 = *(const unsigned long long*)(whid + i * IN_STRIDE);
            unsigned long long h1 = *(const unsigned long long*)(whid + i * IN_STRIDE + 2);
            const float* wr = W2s + i * HID + lane;
#pragma unroll
            for (int j = 0; j < 2; j++) {
                unsigned long long w = dup2(wr[32 * j]);
                acc2[j][0] = fma2(w, h0, acc2[j][0]);
                acc2[j][1] = fma2(w, h1, acc2[j][1]);
            }
        }
#pragma unroll
        for (int j = 0; j < 2; j++) {
            int ch = lane + 32 * j;
            float b = b2s[ch];
            float2 f0 = unpk(acc2[j][0]);
            float2 f1 = unpk(acc2[j][1]);
            atomicAdd(&g_m[d[0] * HID + ch], f0.x + b);
            atomicAdd(&g_m[d[1] * HID + ch], f0.y + b);
            atomicAdd(&g_m[d[2] * HID + ch], f1.x + b);
            atomicAdd(&g_m[d[3] * HID + ch], f1.y + b);
        }
        __syncwarp();
    }
}

// --------------------------------- GRU -------------------------------------
#define GK_THREADS 256
#define GK_WARPS 8
#define NPW 2
#define GRU_SMEM_F (64 * 192 * 2 + 192 * 2 + GK_WARPS * NPW * 2 * HID)

__global__ __launch_bounds__(GK_THREADS, 2)
void gru_kernel(const float* __restrict__ Wih, const float* __restrict__ Whh,
                const float* __restrict__ bih, const float* __restrict__ bhh) {
    extern __shared__ float s[];
    float* WihT = s;                    // [c(64)][g(192)]
    float* WhhT = WihT + 64 * 192;
    float* bihs = WhhT + 64 * 192;      // 192
    float* bhhs = bihs + 192;           // 192
    float* stg  = bhhs + 192;           // [warp][NPW][128]

    int tid = threadIdx.x;
    for (int idx = tid; idx < 192 * 64; idx += GK_THREADS) {
        int g = idx >> 6, c = idx & 63;
        WihT[c * 192 + g] = Wih[idx];
        WhhT[c * 192 + g] = Whh[idx];
    }
    for (int idx = tid; idx < 192; idx += GK_THREADS) {
        bihs[idx] = bih[idx];
        bhhs[idx] = bhh[idx];
    }
    __syncthreads();

    int warp = tid >> 5, lane = tid & 31;
    float* ws = stg + warp * NPW * 2 * HID;
    const int npairs = N_NODES / NPW;

    for (int p = blockIdx.x * GK_WARPS + warp; p < npairs;
         p += gridDim.x * GK_WARPS) {
        int v0 = p * NPW;
#pragma unroll
        for (int n = 0; n < NPW; n++) {
            int v = v0 + n;
            ws[n * 128 + lane]      = g_m[v * HID + lane];
            ws[n * 128 + lane + 32] = g_m[v * HID + lane + 32];
            ws[n * 128 + 64 + lane]      = g_x[v * HID + lane];
            ws[n * 128 + 64 + lane + 32] = g_x[v * HID + lane + 32];
        }
        __syncwarp();

        float ai[NPW][6], ah[NPW][6];
#pragma unroll
        for (int n = 0; n < NPW; n++)
#pragma unroll
            for (int j = 0; j < 6; j++) { ai[n][j] = 0.f; ah[n][j] = 0.f; }

#pragma unroll 2
        for (int c = 0; c < HID; c++) {
            const float* wi = &WihT[c * 192 + lane];
            const float* wh = &WhhT[c * 192 + lane];
#pragma unroll
            for (int n = 0; n < NPW; n++) {
                float mv = ws[n * 128 + c];
                float hv = ws[n * 128 + 64 + c];
#pragma unroll
                for (int j = 0; j < 6; j++) {
                    ai[n][j] += mv * wi[32 * j];
                    ah[n][j] += hv * wh[32 * j];
                }
            }
        }
#pragma unroll
        for (int n = 0; n < NPW; n++) {
            int v = v0 + n;
#pragma unroll
            for (int j2 = 0; j2 < 2; j2++) {
                int ch = lane + 32 * j2;
                float r = sigmoidf_(ai[n][j2] + bihs[ch] + ah[n][j2] + bhhs[ch]);
                float z = sigmoidf_(ai[n][2 + j2] + bihs[64 + ch] +
                                    ah[n][2 + j2] + bhhs[64 + ch]);
                float nn = tanhf(ai[n][4 + j2] + bihs[128 + ch] +
                                 r * (ah[n][4 + j2] + bhhs[128 + ch]));
                float hold = ws[n * 128 + 64 + ch];
                g_x[v * HID + ch] = (1.f - z) * nn + z * hold;
            }
        }
        __syncwarp();
    }
}

// ------------------------------- LSTM cell ---------------------------------
#define LSTM_SMEM_F (256 * 128 + 256 * 64 + 4 * 128 + 4 * 64)

__global__ __launch_bounds__(256, 1)
void lstm_kernel(const float* __restrict__ Wih, const float* __restrict__ Whh,
                 const float* __restrict__ bih, const float* __restrict__ bhh) {
    extern __shared__ float s[];
    float* WihT = s;                   // [c(128)][gate(256)]
    float* WhhT = WihT + 256 * 128;    // [c(64)][gate(256)]
    float* qs_s = WhhT + 256 * 64;     // [4][128]
    float* qh_s = qs_s + 4 * 128;      // [4][64]

    int tid = threadIdx.x;
    for (int idx = tid; idx < 256 * 128; idx += 256) {
        int g = idx >> 7, c = idx & 127;
        WihT[c * 256 + g] = Wih[idx];
    }
    for (int idx = tid; idx < 256 * 64; idx += 256) {
        int g = idx >> 6, c = idx & 63;
        WhhT[c * 256 + g] = Whh[idx];
    }
    int g0 = blockIdx.x * 4;
    for (int idx = tid; idx < 4 * 128; idx += 256)
        qs_s[idx] = g_qstar[g0 * 128 + idx];
    for (int idx = tid; idx < 4 * 64; idx += 256)
        qh_s[idx] = g_qh[g0 * 64 + idx];
    __syncthreads();

    int lg = tid >> 6;
    int u = tid & 63;
    int g = g0 + lg;
    float accI = bih[u] + bhh[u];
    float accF = bih[64 + u] + bhh[64 + u];
    float accG = bih[128 + u] + bhh[128 + u];
    float accO = bih[192 + u] + bhh[192 + u];
    const float* qs = qs_s + lg * 128;
#pragma unroll 4
    for (int c = 0; c < 128; c++) {
        float v = qs[c];
        const float* w = &WihT[c * 256];
        accI += v * w[u];
        accF += v * w[64 + u];
        accG += v * w[128 + u];
        accO += v * w[192 + u];
    }
    const float* qh = qh_s + lg * 64;
#pragma unroll 4
    for (int c = 0; c < 64; c++) {
        float v = qh[c];
        const float* w = &WhhT[c * 256];
        accI += v * w[u];
        accF += v * w[64 + u];
        accG += v * w[128 + u];
        accO += v * w[192 + u];
    }
    float i_ = sigmoidf_(accI), f_ = sigmoidf_(accF);
    float gg = tanhf(accG), o_ = sigmoidf_(accO);
    float c_new = f_ * g_qc[g * 64 + u] + i_ * gg;
    float h_new = o_ * tanhf(c_new);
    g_qc[g * 64 + u] = c_new;
    g_qh[g * 64 + u] = h_new;
}

// ----------------------------- attention steps -----------------------------
__global__ void attn_dot_kernel(const int* __restrict__ batch) {
    int wg = (blockIdx.x * blockDim.x + threadIdx.x) >> 5;
    int lane = threadIdx.x & 31;
    if (wg >= N_NODES) return;
    int v = wg;
    int b = batch[v];
    float p = g_x[v * HID + lane] * g_qh[b * HID + lane] +
              g_x[v * HID + lane + 32] * g_qh[b * HID + lane + 32];
#pragma unroll
    for (int o = 16; o; o >>= 1) p += __shfl_down_sync(0xffffffffu, p, o);
    if (lane == 0) {
        g_e[v] = p;
        atomicMax(&g_emax[b], enc_f(p));
    }
}

__global__ void attn_exp_kernel(const int* __restrict__ batch) {
    int v = blockIdx.x * blockDim.x + threadIdx.x;
    if (v >= N_NODES) return;
    int b = batch[v];
    float a = expf(g_e[v] - dec_f(g_emax[b]));
    g_a[v] = a;
    atomicAdd(&g_asum[b], a);
}

__global__ void attn_rvec_kernel(const int* __restrict__ batch) {
    int wg = (blockIdx.x * blockDim.x + threadIdx.x) >> 5;
    int lane = threadIdx.x & 31;
    if (wg >= N_NODES) return;
    int v = wg;
    int b = batch[v];
    float coef = g_a[v] / g_asum[b];
    atomicAdd(&g_rvec[b * HID + lane], coef * g_x[v * HID + lane]);
    atomicAdd(&g_rvec[b * HID + lane + 32], coef * g_x[v * HID + lane + 32]);
}

__global__ void qstar_kernel() {
    int t = blockIdx.x * blockDim.x + threadIdx.x;
    if (t >= NUM_GRAPHS * HID) return;
    int g = t >> 6, u = t & 63;
    g_qstar[g * 2 * HID + u] = g_qh[t];
    g_qstar[g * 2 * HID + HID + u] = g_rvec[t];
}

// ------------------------------- regressor ---------------------------------
__global__ void reg_kernel(const float* __restrict__ W1,
                           const float* __restrict__ b1,
                           const float* __restrict__ W2,
                           const float* __restrict__ b2,
                           float* __restrict__ out) {
    __shared__ float qs[128];
    __shared__ float red[64];
    int g = blockIdx.x;
    int u = threadIdx.x;  // 64 threads
    qs[u] = g_qstar[g * 128 + u];
    qs[u + 64] = g_qstar[g * 128 + u + 64];
    __syncthreads();
    float acc = b1[u];
#pragma unroll 4
    for (int c = 0; c < 128; c++) acc += qs[c] * W1[c * HID + u];
    red[u] = fmaxf(acc, 0.f) * W2[u];
    __syncthreads();
    for (int sft = 32; sft; sft >>= 1) {
        if (u < sft) red[u] += red[u + sft];
        __syncthreads();
    }
    if (u == 0) out[g] = red[0] + b2[0];
}

// ------------------------------ host driver --------------------------------
extern "C" void kernel_launch(void* const* d_in, const int* in_sizes, int n_in,
                              void* d_out, int out_size) {
    const float* x_feat     = (const float*)d_in[0];
    const int*   edge_index = (const int*)d_in[1];
    const float* edge_attr  = (const float*)d_in[2];
    const int*   batch      = (const int*)d_in[3];
    const float* W_emb = (const float*)d_in[4];
    const float* b_emb = (const float*)d_in[5];
    const float* W_m1  = (const float*)d_in[6];
    const float* b_m1  = (const float*)d_in[7];
    const float* W_m2  = (const float*)d_in[8];
    const float* b_m2  = (const float*)d_in[9];
    const float* gWih  = (const float*)d_in[10];
    const float* gWhh  = (const float*)d_in[11];
    const float* gbih  = (const float*)d_in[12];
    const float* gbhh  = (const float*)d_in[13];
    const float* lWih  = (const float*)d_in[14];
    const float* lWhh  = (const float*)d_in[15];
    const float* lbih  = (const float*)d_in[16];
    const float* lbhh  = (const float*)d_in[17];
    const float* Wr1   = (const float*)d_in[18];
    const float* br1   = (const float*)d_in[19];
    const float* Wr2   = (const float*)d_in[20];
    const float* br2   = (const float*)d_in[21];
    float* out = (float*)d_out;

    const int ek_smem   = EK_SMEM_FLOATS * (int)sizeof(float);
    const int gru_smem  = GRU_SMEM_F * (int)sizeof(float);
    const int lstm_smem = LSTM_SMEM_F * (int)sizeof(float);
    cudaFuncSetAttribute(edge_msg_kernel,
                         cudaFuncAttributeMaxDynamicSharedMemorySize, ek_smem);
    cudaFuncSetAttribute(gru_kernel,
                         cudaFuncAttributeMaxDynamicSharedMemorySize, gru_smem);
    cudaFuncSetAttribute(lstm_kernel,
                         cudaFuncAttributeMaxDynamicSharedMemorySize, lstm_smem);

    // 1. node embedding
    embed_kernel<<<(N_NODES * HID + 255) / 256, 256>>>(x_feat, W_emb, b_emb);

    // 2. message passing rounds
    for (int r = 0; r < NUM_MP; r++) {
        zero_m_kernel<<<(N_NODES * HID + 255) / 256, 256>>>();
        edge_msg_kernel<<<148, EK_THREADS, ek_smem>>>(edge_index, edge_attr,
                                                      W_m1, b_m1, W_m2, b_m2);
        gru_kernel<<<296, GK_THREADS, gru_smem>>>(gWih, gWhh, gbih, gbhh);
    }

    // 3. Set2Set
    zero_s2s_state_kernel<<<(NUM_GRAPHS * 2 * HID + 255) / 256, 256>>>();
    for (int s = 0; s < S2S_STEPS; s++) {
        lstm_kernel<<<NUM_GRAPHS / 4, 256, lstm_smem>>>(lWih, lWhh, lbih, lbhh);
        zero_attn_kernel<<<(NUM_GRAPHS * HID + 255) / 256, 256>>>();
        attn_dot_kernel<<<(N_NODES * 32 + 255) / 256, 256>>>(batch);
        attn_exp_kernel<<<(N_NODES + 255) / 256, 256>>>(batch);
        attn_rvec_kernel<<<(N_NODES * 32 + 255) / 256, 256>>>(batch);
        qstar_kernel<<<(NUM_GRAPHS * HID + 255) / 256, 256>>>();
    }

    // 4. regressor
    reg_kernel<<<NUM_GRAPHS, 64>>>(Wr1, br1, Wr2, br2, out);
    (void)in_sizes; (void)n_in; (void)out_size;
}